// round 12
// baseline (speedup 1.0000x reference)
#include <cuda_runtime.h>
#include <cuda_fp16.h>
#include <math.h>
#include <stdint.h>

#define N_TOK 4096      // B*T
#define DDIM  1024
#define HDIM  4096
#define NEXP  8
#define NSLOT (N_TOK * 2)
#define KSPL  4                      // GEMM2 split-K factor
#define PSTRIDE ((size_t)NSLOT * DDIM)

// ---------------- scratch (static device globals; no cudaMalloc) ----------
__device__ __half g_hh[(size_t)NSLOT * HDIM];          //  64 MB : gelu out (fp16)
__device__ float  g_eo[(size_t)KSPL * NSLOT * DDIM];   // 128 MB : GEMM2 partials
__device__ __half g_xh[(size_t)N_TOK * DDIM];          //   8 MB : x (fp16)
__device__ __half g_w1h[(size_t)NEXP * DDIM * HDIM];   //  64 MB : W1 fp16
__device__ __half g_w2h[(size_t)NEXP * DDIM * HDIM];   //  64 MB : W2 fp16
__device__ int   g_perm[NSLOT];
__device__ int   g_slot_of[NSLOT];
__device__ int   g_tope[NSLOT];
__device__ float g_topw[NSLOT];
__device__ int   g_cnt[NEXP];
__device__ int   g_off[NEXP];

// ======================= PTX helpers (compute_103-safe) ====================
__device__ __forceinline__ uint32_t smem_u32(const void* p) {
    uint32_t a;
    asm("{ .reg .u64 t; cvta.to.shared.u64 t, %1; cvt.u32.u64 %0, t; }"
        : "=r"(a) : "l"(p));
    return a;
}
__device__ __forceinline__ void cp_async16(uint32_t dst, const void* src, uint32_t sz) {
    asm volatile("cp.async.ca.shared.global [%0], [%1], 16, %2;"
                 :: "r"(dst), "l"(src), "r"(sz) : "memory");
}
#define CP_COMMIT() asm volatile("cp.async.commit_group;" ::: "memory")
#define CP_WAIT(n)  asm volatile("cp.async.wait_group %0;" :: "n"(n) : "memory")

__device__ __forceinline__ void ldsm_x4(uint32_t* r, uint32_t addr) {
    asm volatile("ldmatrix.sync.aligned.m8n8.x4.shared.b16 {%0,%1,%2,%3}, [%4];"
                 : "=r"(r[0]), "=r"(r[1]), "=r"(r[2]), "=r"(r[3]) : "r"(addr));
}
__device__ __forceinline__ void ldsm_x4_t(uint32_t* r, uint32_t addr) {
    asm volatile("ldmatrix.sync.aligned.m8n8.x4.trans.shared.b16 {%0,%1,%2,%3}, [%4];"
                 : "=r"(r[0]), "=r"(r[1]), "=r"(r[2]), "=r"(r[3]) : "r"(addr));
}
__device__ __forceinline__ void mma_f16(float* d, const uint32_t* a,
                                        uint32_t b0, uint32_t b1) {
    asm volatile(
        "mma.sync.aligned.m16n8k16.row.col.f32.f16.f16.f32 "
        "{%0,%1,%2,%3}, {%4,%5,%6,%7}, {%8,%9}, {%0,%1,%2,%3};"
        : "+f"(d[0]), "+f"(d[1]), "+f"(d[2]), "+f"(d[3])
        : "r"(a[0]), "r"(a[1]), "r"(a[2]), "r"(a[3]), "r"(b0), "r"(b1));
}
// exact gelu via erff (no erfc range-reduction/exp path)
__device__ __forceinline__ float gelu_erf(float v) {
    return 0.5f * v * (1.0f + erff(v * 0.70710678118654752f));
}

// ======================= small kernels ======================================
__global__ void reset_kernel() {
    int i = threadIdx.x;
    if (i < NEXP) g_cnt[i] = 0;
}

// 8 warps/block, 1 token/warp; fused x->fp16 conversion (x is read anyway)
__global__ void gate_kernel(const float* __restrict__ x,
                            const float* __restrict__ Wg,
                            const float* __restrict__ bg,
                            __half* __restrict__ xh) {
    int wid = threadIdx.x >> 5;
    int lane = threadIdx.x & 31;
    int t = blockIdx.x * 8 + wid;
    const float* xr = x + (size_t)t * DDIM;
    __half* xo = xh + (size_t)t * DDIM;
    float p[NEXP];
#pragma unroll
    for (int e = 0; e < NEXP; e++) p[e] = 0.f;
#pragma unroll
    for (int it = 0; it < DDIM / 128; it++) {
        int d = it * 128 + lane * 4;
        float4 v = *reinterpret_cast<const float4*>(xr + d);
        __half2 h0 = __floats2half2_rn(v.x, v.y);
        __half2 h1 = __floats2half2_rn(v.z, v.w);
        uint2 u;
        u.x = *reinterpret_cast<uint32_t*>(&h0);
        u.y = *reinterpret_cast<uint32_t*>(&h1);
        *reinterpret_cast<uint2*>(xo + d) = u;
        float vv[4] = {v.x, v.y, v.z, v.w};
#pragma unroll
        for (int j = 0; j < 4; j++) {
            const float4* w4 = reinterpret_cast<const float4*>(Wg + (size_t)(d + j) * NEXP);
            float4 a = w4[0], b = w4[1];
            float xv = vv[j];
            p[0] += xv * a.x; p[1] += xv * a.y; p[2] += xv * a.z; p[3] += xv * a.w;
            p[4] += xv * b.x; p[5] += xv * b.y; p[6] += xv * b.z; p[7] += xv * b.w;
        }
    }
#pragma unroll
    for (int off = 16; off; off >>= 1)
#pragma unroll
        for (int e = 0; e < NEXP; e++)
            p[e] += __shfl_xor_sync(0xffffffffu, p[e], off);
    if (lane == 0) {
#pragma unroll
        for (int e = 0; e < NEXP; e++) p[e] += bg[e];
        int i0 = 0;
#pragma unroll
        for (int e = 1; e < NEXP; e++) if (p[e] > p[i0]) i0 = e;
        int i1 = (i0 == 0) ? 1 : 0;
#pragma unroll
        for (int e = 0; e < NEXP; e++)
            if (e != i0 && p[e] > p[i1]) i1 = e;
        float e1 = expf(p[i1] - p[i0]);
        float w0 = 1.0f / (1.0f + e1);
        float w1 = e1 / (1.0f + e1);
        g_tope[t * 2 + 0] = i0;  g_tope[t * 2 + 1] = i1;
        g_topw[t * 2 + 0] = w0;  g_topw[t * 2 + 1] = w1;
        atomicAdd(&g_cnt[i0], 1);
        atomicAdd(&g_cnt[i1], 1);
    }
}

// single block: prefix offsets + scatter (smem counters)
__global__ void offsets_scatter_kernel() {
    __shared__ int s_off[NEXP];
    __shared__ int s_cur[NEXP];
    if (threadIdx.x == 0) {
        int acc = 0;
        for (int e = 0; e < NEXP; e++) {
            s_off[e] = acc; g_off[e] = acc; acc += g_cnt[e]; s_cur[e] = 0;
        }
    }
    __syncthreads();
    for (int t = threadIdx.x; t < N_TOK; t += blockDim.x) {
#pragma unroll
        for (int k = 0; k < 2; k++) {
            int e = g_tope[t * 2 + k];
            int pos = s_off[e] + atomicAdd(&s_cur[e], 1);
            g_perm[pos] = t;
            g_slot_of[t * 2 + k] = pos;
        }
    }
}

// ---------------- fp32 -> fp16 elementwise (weights) ------------------------
__global__ void conv_half_kernel(const float* __restrict__ in,
                                 __half* __restrict__ out) {
    size_t i = (size_t)(blockIdx.x * blockDim.x + threadIdx.x) * 8;
    float4 v0 = *reinterpret_cast<const float4*>(in + i);
    float4 v1 = *reinterpret_cast<const float4*>(in + i + 4);
    __half2 h[4];
    h[0] = __floats2half2_rn(v0.x, v0.y);
    h[1] = __floats2half2_rn(v0.z, v0.w);
    h[2] = __floats2half2_rn(v1.x, v1.y);
    h[3] = __floats2half2_rn(v1.z, v1.w);
    *reinterpret_cast<uint4*>(out + i) = *reinterpret_cast<uint4*>(h);
}

// ======================= fp16 mma.sync grouped GEMM =========================
// CTA tile 128(M) x 256(N), k-chunk 64, 8 warps (2m x 4n), warp tile 64x64.
// 4-stage cp.async pipeline, ONE barrier per chunk. Optional split-K:
// grid.z = NEXP*KSPLIT; slice ksl covers k in [ksl*KDIM, (ksl+1)*KDIM),
// writes partial buffer Out + ksl*PSTRIDE; bias added only in slice 0.
#define ASTAGE_B 16384
#define BSTAGE_B 32768
#define OFF_A    1024
#define OFF_B    (OFF_A + 4 * ASTAGE_B)        // 66560
#define SM_BYTES (OFF_B + 4 * BSTAGE_B)        // 197632

template <int KDIM, int KSTRIDE, int KSPLIT, bool GATHER, bool DOGELU, typename OutT>
__global__ __launch_bounds__(256) void moe_gemm(
    const __half* __restrict__ Ah, const __half* __restrict__ Bh,
    const float* __restrict__ bias, OutT* __restrict__ Out, int Ntot) {
    extern __shared__ char smem[];
    const int e = blockIdx.z / KSPLIT;
    const int ksl = blockIdx.z % KSPLIT;
    const int cnt = g_cnt[e];
    const int m0 = blockIdx.x * 128;
    if (m0 >= cnt) return;
    const int off = g_off[e];
    const int n0 = blockIdx.y * 256;
    const __half* Asl = Ah + (size_t)ksl * KDIM;                     // k-slice base
    const __half* Bte = Bh + (size_t)e * KSTRIDE * Ntot
                           + (size_t)ksl * KDIM * Ntot;              // [K][Ntot]
    OutT* Osl = Out + (KSPLIT > 1 ? (size_t)ksl * PSTRIDE : 0);
    const bool addb = (ksl == 0);

    const uint32_t sb = smem_u32(smem);
    const int tid = threadIdx.x;
    const int wid = tid >> 5, lane = tid & 31;
    const int wm = wid & 1, wn = wid >> 1;
    const int m_base = wm * 64, n_base = wn * 64;

    int* rowtok = (int*)smem;
    if (GATHER && tid < 128) {
        int r = m0 + tid;
        rowtok[tid] = (r < cnt) ? g_perm[off + r] : -1;
    }
    __syncthreads();

    constexpr int NC = KDIM / 64;

    auto load_chunk = [&](int c) {
        const int s = c & 3;
        const int k0 = c * 64;
        const uint32_t Abs = sb + OFF_A + s * ASTAGE_B;
        const uint32_t Bbs = sb + OFF_B + s * BSTAGE_B;
#pragma unroll
        for (int f = 0; f < 4; f++) {
            int id = tid + f * 256;
            int row = id >> 3, g = id & 7;
            uint32_t sz = 16;
            const char* src;
            if (GATHER) {
                int tok = rowtok[row];
                if (tok < 0) { sz = 0; tok = 0; }
                src = (const char*)(Asl + (size_t)tok * KSTRIDE + k0) + g * 16;
            } else {
                int mr = m0 + row;
                if (mr >= cnt) { sz = 0; mr = 0; }
                src = (const char*)(Asl + (size_t)(off + mr) * KSTRIDE + k0) + g * 16;
            }
            cp_async16(Abs + row * 128 + ((g ^ (row & 7)) << 4), src, sz);
        }
#pragma unroll
        for (int f = 0; f < 8; f++) {
            int id = tid + f * 256;
            int krow = id >> 5, g = id & 31;
            const char* src =
                (const char*)(Bte + (size_t)(k0 + krow) * Ntot + n0) + g * 16;
            cp_async16(Bbs + krow * 512 + ((g ^ (krow & 7)) << 4), src, 16);
        }
        CP_COMMIT();
    };

    float acc[4][8][4];
#pragma unroll
    for (int mi = 0; mi < 4; mi++)
#pragma unroll
        for (int ni = 0; ni < 8; ni++)
#pragma unroll
            for (int q = 0; q < 4; q++) acc[mi][ni][q] = 0.f;

    load_chunk(0);
    load_chunk(1);
    load_chunk(2);

    const int rowsel = ((lane >> 3) & 1) * 8 + (lane & 7);
    const int gsel = (lane >> 4);
    const int bksel = lane & 15;
    const int bgsel = lane >> 4;

#pragma unroll 1
    for (int c = 0; c < NC; c++) {
        if (c + 2 < NC)      { CP_WAIT(2); }
        else if (c + 1 < NC) { CP_WAIT(1); }
        else                 { CP_WAIT(0); }
        __syncthreads();
        if (c + 3 < NC) load_chunk(c + 3);

        const uint32_t Abs = sb + OFF_A + (c & 3) * ASTAGE_B;
        const uint32_t Bbs = sb + OFF_B + (c & 3) * BSTAGE_B;
#pragma unroll
        for (int ks = 0; ks < 4; ks++) {
            const int ga = ks * 2 + gsel;
            uint32_t a[4][4];
#pragma unroll
            for (int mi = 0; mi < 4; mi++) {
                int row = m_base + mi * 16 + rowsel;
                ldsm_x4(a[mi], Abs + row * 128 + ((ga ^ (row & 7)) << 4));
            }
            const int krow = ks * 16 + bksel;
            uint32_t b[4][4];
#pragma unroll
            for (int nq = 0; nq < 4; nq++) {
                int g = wn * 8 + nq * 2 + bgsel;
                ldsm_x4_t(b[nq], Bbs + krow * 512 + ((g ^ (krow & 7)) << 4));
            }
#pragma unroll
            for (int mi = 0; mi < 4; mi++)
#pragma unroll
                for (int nq = 0; nq < 4; nq++) {
                    mma_f16(acc[mi][2 * nq + 0], a[mi], b[nq][0], b[nq][1]);
                    mma_f16(acc[mi][2 * nq + 1], a[mi], b[nq][2], b[nq][3]);
                }
        }
    }

    // ---- epilogue: (bias) (+gelu via erff) + store ----
    const int lr = lane >> 2;
    const int lc = (lane & 3) * 2;
    float2 bv[8];
#pragma unroll
    for (int ni = 0; ni < 8; ni++) {
        if (addb) {
            int col = n0 + n_base + ni * 8 + lc;
            const float* bp = bias + (size_t)e * Ntot + col;
            bv[ni] = make_float2(bp[0], bp[1]);
        } else {
            bv[ni] = make_float2(0.f, 0.f);
        }
    }
#pragma unroll
    for (int mi = 0; mi < 4; mi++) {
        int r0 = m0 + m_base + mi * 16 + lr;
        int r1 = r0 + 8;
        bool v0 = r0 < cnt, v1 = r1 < cnt;
        OutT* o0 = Osl + (size_t)(off + r0) * Ntot + n0 + n_base + lc;
        OutT* o1 = Osl + (size_t)(off + r1) * Ntot + n0 + n_base + lc;
#pragma unroll
        for (int ni = 0; ni < 8; ni++) {
            if (v0) {
                float x0 = acc[mi][ni][0] + bv[ni].x;
                float x1 = acc[mi][ni][1] + bv[ni].y;
                if (DOGELU) { x0 = gelu_erf(x0); x1 = gelu_erf(x1); }
                if (sizeof(OutT) == 2)
                    *reinterpret_cast<__half2*>(o0 + ni * 8) = __floats2half2_rn(x0, x1);
                else
                    *reinterpret_cast<float2*>(o0 + ni * 8) = make_float2(x0, x1);
            }
            if (v1) {
                float x2 = acc[mi][ni][2] + bv[ni].x;
                float x3 = acc[mi][ni][3] + bv[ni].y;
                if (DOGELU) { x2 = gelu_erf(x2); x3 = gelu_erf(x3); }
                if (sizeof(OutT) == 2)
                    *reinterpret_cast<__half2*>(o1 + ni * 8) = __floats2half2_rn(x2, x3);
                else
                    *reinterpret_cast<float2*>(o1 + ni * 8) = make_float2(x2, x3);
            }
        }
    }
}

// ---- combine: out[t] = w0*Σs eo[s][slot0] + w1*Σs eo[s][slot1] -------------
__global__ void combine_kernel(float* __restrict__ out) {
    int t = blockIdx.x;
    int s0 = g_slot_of[t * 2 + 0], s1 = g_slot_of[t * 2 + 1];
    float w0 = g_topw[t * 2 + 0], w1 = g_topw[t * 2 + 1];
    int i = threadIdx.x;                  // 256 threads, one float4 each
    const float* b0 = g_eo + (size_t)s0 * DDIM + i * 4;
    const float* b1 = g_eo + (size_t)s1 * DDIM + i * 4;
    float rx = 0.f, ry = 0.f, rz = 0.f, rw = 0.f;
#pragma unroll
    for (int s = 0; s < KSPL; s++) {
        float4 a = *reinterpret_cast<const float4*>(b0 + s * PSTRIDE);
        float4 b = *reinterpret_cast<const float4*>(b1 + s * PSTRIDE);
        rx += w0 * a.x + w1 * b.x;
        ry += w0 * a.y + w1 * b.y;
        rz += w0 * a.z + w1 * b.z;
        rw += w0 * a.w + w1 * b.w;
    }
    *reinterpret_cast<float4*>(out + (size_t)t * DDIM + i * 4) =
        make_float4(rx, ry, rz, rw);
}

// ---------------- launch ----------------------------------------------------
struct AuxRes {
    cudaStream_t s2;
    cudaEvent_t fork, w1, w2;
    AuxRes() {
        cudaStreamCreateWithFlags(&s2, cudaStreamNonBlocking);
        cudaEventCreateWithFlags(&fork, cudaEventDisableTiming);
        cudaEventCreateWithFlags(&w1, cudaEventDisableTiming);
        cudaEventCreateWithFlags(&w2, cudaEventDisableTiming);
    }
};

extern "C" void kernel_launch(void* const* d_in, const int* in_sizes, int n_in,
                              void* d_out, int out_size) {
    const float* x  = (const float*)d_in[0];
    const float* Wg = (const float*)d_in[1];
    const float* bg = (const float*)d_in[2];
    const float* W1 = (const float*)d_in[3];
    const float* b1 = (const float*)d_in[4];
    const float* W2 = (const float*)d_in[5];
    const float* b2 = (const float*)d_in[6];
    float* out = (float*)d_out;

    static AuxRes R;   // magic-static init on first (correctness) call

    void *p_hh, *p_eo, *p_xh, *p_w1h, *p_w2h;
    cudaGetSymbolAddress(&p_hh,  g_hh);
    cudaGetSymbolAddress(&p_eo,  g_eo);
    cudaGetSymbolAddress(&p_xh,  g_xh);
    cudaGetSymbolAddress(&p_w1h, g_w1h);
    cudaGetSymbolAddress(&p_w2h, g_w2h);

    cudaFuncSetAttribute(moe_gemm<DDIM, DDIM, 1, true, true, __half>,
                         cudaFuncAttributeMaxDynamicSharedMemorySize, SM_BYTES);
    cudaFuncSetAttribute(moe_gemm<HDIM / KSPL, HDIM, KSPL, false, false, float>,
                         cudaFuncAttributeMaxDynamicSharedMemorySize, SM_BYTES);

    // ---- fork: weight conversions on side stream ----
    cudaEventRecord(R.fork, 0);
    cudaStreamWaitEvent(R.s2, R.fork, 0);
    conv_half_kernel<<<((size_t)NEXP * DDIM * HDIM / 8) / 256, 256, 0, R.s2>>>(
        W1, (__half*)p_w1h);
    cudaEventRecord(R.w1, R.s2);
    conv_half_kernel<<<((size_t)NEXP * DDIM * HDIM / 8) / 256, 256, 0, R.s2>>>(
        W2, (__half*)p_w2h);
    cudaEventRecord(R.w2, R.s2);

    // ---- main stream: gating chain (x conversion fused into gate) ----
    reset_kernel<<<1, 32>>>();
    gate_kernel<<<N_TOK / 8, 256>>>(x, Wg, bg, (__half*)p_xh);
    offsets_scatter_kernel<<<1, 1024>>>();

    // ---- join W1, GEMM1: h = fp16(gelu(x[perm] @ W1 + b1)) ----
    cudaStreamWaitEvent(0, R.w1, 0);
    moe_gemm<DDIM, DDIM, 1, true, true, __half>
        <<<dim3(32, HDIM / 256, NEXP), 256, SM_BYTES>>>(
        (const __half*)p_xh, (const __half*)p_w1h, b1, (__half*)p_hh, HDIM);

    // ---- join W2, GEMM2 (split-K4 partials): eo[s] = h_slice @ W2_slice ----
    cudaStreamWaitEvent(0, R.w2, 0);
    moe_gemm<HDIM / KSPL, HDIM, KSPL, false, false, float>
        <<<dim3(32, DDIM / 256, NEXP * KSPL), 256, SM_BYTES>>>(
        (const __half*)p_hh, (const __half*)p_w2h, b2, (float*)p_eo, DDIM);

    combine_kernel<<<N_TOK, 256>>>(out);
}

// round 13
// speedup vs baseline: 1.0611x; 1.0611x over previous
#include <cuda_runtime.h>
#include <cuda_fp16.h>
#include <math.h>
#include <stdint.h>

#define N_TOK 4096      // B*T
#define DDIM  1024
#define HDIM  4096
#define NEXP  8
#define NSLOT (N_TOK * 2)

// ---------------- scratch (static device globals; no cudaMalloc) ----------
__device__ __half g_hh[(size_t)NSLOT * HDIM];         // 64 MB : gelu out (fp16)
__device__ __half g_xh[(size_t)N_TOK * DDIM];         //  8 MB : x (fp16)
__device__ __half g_w1h[(size_t)NEXP * DDIM * HDIM];  // 64 MB : W1 fp16
__device__ __half g_w2h[(size_t)NEXP * DDIM * HDIM];  // 64 MB : W2 fp16
__device__ int   g_perm[NSLOT];                       // slot -> token
__device__ float g_wslot[NSLOT];                      // slot -> gate weight
__device__ int   g_tope[NSLOT];
__device__ float g_topw[NSLOT];
__device__ int   g_cnt[NEXP];
__device__ int   g_off[NEXP];

// ======================= PTX helpers (compute_103-safe) ====================
__device__ __forceinline__ uint32_t smem_u32(const void* p) {
    uint32_t a;
    asm("{ .reg .u64 t; cvta.to.shared.u64 t, %1; cvt.u32.u64 %0, t; }"
        : "=r"(a) : "l"(p));
    return a;
}
__device__ __forceinline__ void cp_async16(uint32_t dst, const void* src, uint32_t sz) {
    asm volatile("cp.async.ca.shared.global [%0], [%1], 16, %2;"
                 :: "r"(dst), "l"(src), "r"(sz) : "memory");
}
#define CP_COMMIT() asm volatile("cp.async.commit_group;" ::: "memory")
#define CP_WAIT(n)  asm volatile("cp.async.wait_group %0;" :: "n"(n) : "memory")

__device__ __forceinline__ void ldsm_x4(uint32_t* r, uint32_t addr) {
    asm volatile("ldmatrix.sync.aligned.m8n8.x4.shared.b16 {%0,%1,%2,%3}, [%4];"
                 : "=r"(r[0]), "=r"(r[1]), "=r"(r[2]), "=r"(r[3]) : "r"(addr));
}
__device__ __forceinline__ void ldsm_x4_t(uint32_t* r, uint32_t addr) {
    asm volatile("ldmatrix.sync.aligned.m8n8.x4.trans.shared.b16 {%0,%1,%2,%3}, [%4];"
                 : "=r"(r[0]), "=r"(r[1]), "=r"(r[2]), "=r"(r[3]) : "r"(addr));
}
__device__ __forceinline__ void mma_f16(float* d, const uint32_t* a,
                                        uint32_t b0, uint32_t b1) {
    asm volatile(
        "mma.sync.aligned.m16n8k16.row.col.f32.f16.f16.f32 "
        "{%0,%1,%2,%3}, {%4,%5,%6,%7}, {%8,%9}, {%0,%1,%2,%3};"
        : "+f"(d[0]), "+f"(d[1]), "+f"(d[2]), "+f"(d[3])
        : "r"(a[0]), "r"(a[1]), "r"(a[2]), "r"(a[3]), "r"(b0), "r"(b1));
}
// exact gelu via erff (no erfc range-reduction/exp path)
__device__ __forceinline__ float gelu_erf(float v) {
    return 0.5f * v * (1.0f + erff(v * 0.70710678118654752f));
}

// ======================= small kernels ======================================
__global__ void reset_kernel() {
    int i = threadIdx.x;
    if (i < NEXP) g_cnt[i] = 0;
}

__global__ void zero_out_kernel(float* __restrict__ out) {
    size_t i = (size_t)(blockIdx.x * blockDim.x + threadIdx.x) * 4;
    *reinterpret_cast<float4*>(out + i) = make_float4(0.f, 0.f, 0.f, 0.f);
}

// 8 warps per block, one token per warp (R11 version — unfused)
__global__ void gate_kernel(const float* __restrict__ x,
                            const float* __restrict__ Wg,
                            const float* __restrict__ bg) {
    int wid = threadIdx.x >> 5;
    int lane = threadIdx.x & 31;
    int t = blockIdx.x * 8 + wid;
    if (t >= N_TOK) return;
    const float* xr = x + (size_t)t * DDIM;
    float p[NEXP];
#pragma unroll
    for (int e = 0; e < NEXP; e++) p[e] = 0.f;
    for (int d = lane; d < DDIM; d += 32) {
        float xv = xr[d];
        const float4* w4 = reinterpret_cast<const float4*>(Wg + (size_t)d * NEXP);
        float4 a = w4[0], b = w4[1];
        p[0] += xv * a.x; p[1] += xv * a.y; p[2] += xv * a.z; p[3] += xv * a.w;
        p[4] += xv * b.x; p[5] += xv * b.y; p[6] += xv * b.z; p[7] += xv * b.w;
    }
#pragma unroll
    for (int off = 16; off; off >>= 1)
#pragma unroll
        for (int e = 0; e < NEXP; e++)
            p[e] += __shfl_xor_sync(0xffffffffu, p[e], off);
    if (lane == 0) {
#pragma unroll
        for (int e = 0; e < NEXP; e++) p[e] += bg[e];
        int i0 = 0;
#pragma unroll
        for (int e = 1; e < NEXP; e++) if (p[e] > p[i0]) i0 = e;
        int i1 = (i0 == 0) ? 1 : 0;
#pragma unroll
        for (int e = 0; e < NEXP; e++)
            if (e != i0 && p[e] > p[i1]) i1 = e;
        float e1 = expf(p[i1] - p[i0]);
        float w0 = 1.0f / (1.0f + e1);
        float w1 = e1 / (1.0f + e1);
        g_tope[t * 2 + 0] = i0;  g_tope[t * 2 + 1] = i1;
        g_topw[t * 2 + 0] = w0;  g_topw[t * 2 + 1] = w1;
        atomicAdd(&g_cnt[i0], 1);
        atomicAdd(&g_cnt[i1], 1);
    }
}

// single block: prefix offsets + scatter (smem counters)
__global__ void offsets_scatter_kernel() {
    __shared__ int s_off[NEXP];
    __shared__ int s_cur[NEXP];
    if (threadIdx.x == 0) {
        int acc = 0;
        for (int e = 0; e < NEXP; e++) {
            s_off[e] = acc; g_off[e] = acc; acc += g_cnt[e]; s_cur[e] = 0;
        }
    }
    __syncthreads();
    for (int t = threadIdx.x; t < N_TOK; t += blockDim.x) {
#pragma unroll
        for (int k = 0; k < 2; k++) {
            int e = g_tope[t * 2 + k];
            int pos = s_off[e] + atomicAdd(&s_cur[e], 1);
            g_perm[pos] = t;
            g_wslot[pos] = g_topw[t * 2 + k];
        }
    }
}

// ---------------- fp32 -> fp16 elementwise (8 elems/thread) ----------------
__global__ void conv_half_kernel(const float* __restrict__ in,
                                 __half* __restrict__ out) {
    size_t i = (size_t)(blockIdx.x * blockDim.x + threadIdx.x) * 8;
    float4 v0 = *reinterpret_cast<const float4*>(in + i);
    float4 v1 = *reinterpret_cast<const float4*>(in + i + 4);
    __half2 h[4];
    h[0] = __floats2half2_rn(v0.x, v0.y);
    h[1] = __floats2half2_rn(v0.z, v0.w);
    h[2] = __floats2half2_rn(v1.x, v1.y);
    h[3] = __floats2half2_rn(v1.z, v1.w);
    *reinterpret_cast<uint4*>(out + i) = *reinterpret_cast<uint4*>(h);
}

// ======================= fp16 mma.sync grouped GEMM =========================
// CTA tile 128(M) x 256(N), k-chunk 64, 8 warps (2m x 4n), warp tile 64x64.
// 4-stage cp.async pipeline, ONE barrier per chunk.
// FUSE=true (GEMM2): epilogue scatters w*(acc+bias) into out[token] by atomicAdd.
#define ASTAGE_B 16384
#define BSTAGE_B 32768
#define OFF_A    1024
#define OFF_B    (OFF_A + 4 * ASTAGE_B)        // 66560
#define SM_BYTES (OFF_B + 4 * BSTAGE_B)        // 197632

template <int KDIM, bool GATHER, bool DOGELU, bool FUSE, typename OutT>
__global__ __launch_bounds__(256) void moe_gemm(
    const __half* __restrict__ Ah, const __half* __restrict__ Bh,
    const float* __restrict__ bias, OutT* __restrict__ Out, int Ntot) {
    extern __shared__ char smem[];
    const int e = blockIdx.z;
    const int cnt = g_cnt[e];
    const int m0 = blockIdx.x * 128;
    if (m0 >= cnt) return;
    const int off = g_off[e];
    const int n0 = blockIdx.y * 256;
    const __half* Bte = Bh + (size_t)e * KDIM * Ntot;   // [K][Ntot]

    const uint32_t sb = smem_u32(smem);
    const int tid = threadIdx.x;
    const int wid = tid >> 5, lane = tid & 31;
    const int wm = wid & 1, wn = wid >> 1;
    const int m_base = wm * 64, n_base = wn * 64;

    int* rowtok = (int*)smem;
    if (GATHER && tid < 128) {
        int r = m0 + tid;
        rowtok[tid] = (r < cnt) ? g_perm[off + r] : -1;
    }
    __syncthreads();

    constexpr int NC = KDIM / 64;

    auto load_chunk = [&](int c) {
        const int s = c & 3;
        const int k0 = c * 64;
        const uint32_t Abs = sb + OFF_A + s * ASTAGE_B;
        const uint32_t Bbs = sb + OFF_B + s * BSTAGE_B;
#pragma unroll
        for (int f = 0; f < 4; f++) {
            int id = tid + f * 256;
            int row = id >> 3, g = id & 7;
            uint32_t sz = 16;
            const char* src;
            if (GATHER) {
                int tok = rowtok[row];
                if (tok < 0) { sz = 0; tok = 0; }
                src = (const char*)(Ah + (size_t)tok * KDIM + k0) + g * 16;
            } else {
                int mr = m0 + row;
                if (mr >= cnt) { sz = 0; mr = 0; }
                src = (const char*)(Ah + (size_t)(off + mr) * KDIM + k0) + g * 16;
            }
            cp_async16(Abs + row * 128 + ((g ^ (row & 7)) << 4), src, sz);
        }
#pragma unroll
        for (int f = 0; f < 8; f++) {
            int id = tid + f * 256;
            int krow = id >> 5, g = id & 31;
            const char* src =
                (const char*)(Bte + (size_t)(k0 + krow) * Ntot + n0) + g * 16;
            cp_async16(Bbs + krow * 512 + ((g ^ (krow & 7)) << 4), src, 16);
        }
        CP_COMMIT();
    };

    float acc[4][8][4];
#pragma unroll
    for (int mi = 0; mi < 4; mi++)
#pragma unroll
        for (int ni = 0; ni < 8; ni++)
#pragma unroll
            for (int q = 0; q < 4; q++) acc[mi][ni][q] = 0.f;

    load_chunk(0);
    load_chunk(1);
    load_chunk(2);

    const int rowsel = ((lane >> 3) & 1) * 8 + (lane & 7);
    const int gsel = (lane >> 4);
    const int bksel = lane & 15;
    const int bgsel = lane >> 4;

#pragma unroll 1
    for (int c = 0; c < NC; c++) {
        if (c + 2 < NC)      { CP_WAIT(2); }
        else if (c + 1 < NC) { CP_WAIT(1); }
        else                 { CP_WAIT(0); }
        __syncthreads();
        if (c + 3 < NC) load_chunk(c + 3);

        const uint32_t Abs = sb + OFF_A + (c & 3) * ASTAGE_B;
        const uint32_t Bbs = sb + OFF_B + (c & 3) * BSTAGE_B;
#pragma unroll
        for (int ks = 0; ks < 4; ks++) {
            const int ga = ks * 2 + gsel;
            uint32_t a[4][4];
#pragma unroll
            for (int mi = 0; mi < 4; mi++) {
                int row = m_base + mi * 16 + rowsel;
                ldsm_x4(a[mi], Abs + row * 128 + ((ga ^ (row & 7)) << 4));
            }
            const int krow = ks * 16 + bksel;
            uint32_t b[4][4];
#pragma unroll
            for (int nq = 0; nq < 4; nq++) {
                int g = wn * 8 + nq * 2 + bgsel;
                ldsm_x4_t(b[nq], Bbs + krow * 512 + ((g ^ (krow & 7)) << 4));
            }
#pragma unroll
            for (int mi = 0; mi < 4; mi++)
#pragma unroll
                for (int nq = 0; nq < 4; nq++) {
                    mma_f16(acc[mi][2 * nq + 0], a[mi], b[nq][0], b[nq][1]);
                    mma_f16(acc[mi][2 * nq + 1], a[mi], b[nq][2], b[nq][3]);
                }
        }
    }

    // ---- epilogue ----
    const int lr = lane >> 2;
    const int lc = (lane & 3) * 2;
    float2 bv[8];
#pragma unroll
    for (int ni = 0; ni < 8; ni++) {
        int col = n0 + n_base + ni * 8 + lc;
        const float* bp = bias + (size_t)e * Ntot + col;
        bv[ni] = make_float2(bp[0], bp[1]);
    }
#pragma unroll
    for (int mi = 0; mi < 4; mi++) {
        int r0 = m0 + m_base + mi * 16 + lr;
        int r1 = r0 + 8;
        bool v0 = r0 < cnt, v1 = r1 < cnt;
        if (FUSE) {
            // fused combine: out[token] += w * (acc + bias), via atomics
            int s0 = off + r0, s1 = off + r1;
            int tok0 = v0 ? g_perm[s0] : 0;
            int tok1 = v1 ? g_perm[s1] : 0;
            float w0 = v0 ? g_wslot[s0] : 0.f;
            float w1 = v1 ? g_wslot[s1] : 0.f;
            float* o0 = (float*)Out + (size_t)tok0 * Ntot + n0 + n_base + lc;
            float* o1 = (float*)Out + (size_t)tok1 * Ntot + n0 + n_base + lc;
#pragma unroll
            for (int ni = 0; ni < 8; ni++) {
                if (v0) {
                    atomicAdd(o0 + ni * 8 + 0, w0 * (acc[mi][ni][0] + bv[ni].x));
                    atomicAdd(o0 + ni * 8 + 1, w0 * (acc[mi][ni][1] + bv[ni].y));
                }
                if (v1) {
                    atomicAdd(o1 + ni * 8 + 0, w1 * (acc[mi][ni][2] + bv[ni].x));
                    atomicAdd(o1 + ni * 8 + 1, w1 * (acc[mi][ni][3] + bv[ni].y));
                }
            }
        } else {
            OutT* o0 = Out + (size_t)(off + r0) * Ntot + n0 + n_base + lc;
            OutT* o1 = Out + (size_t)(off + r1) * Ntot + n0 + n_base + lc;
#pragma unroll
            for (int ni = 0; ni < 8; ni++) {
                if (v0) {
                    float x0 = acc[mi][ni][0] + bv[ni].x;
                    float x1 = acc[mi][ni][1] + bv[ni].y;
                    if (DOGELU) { x0 = gelu_erf(x0); x1 = gelu_erf(x1); }
                    if (sizeof(OutT) == 2)
                        *reinterpret_cast<__half2*>(o0 + ni * 8) = __floats2half2_rn(x0, x1);
                    else
                        *reinterpret_cast<float2*>(o0 + ni * 8) = make_float2(x0, x1);
                }
                if (v1) {
                    float x2 = acc[mi][ni][2] + bv[ni].x;
                    float x3 = acc[mi][ni][3] + bv[ni].y;
                    if (DOGELU) { x2 = gelu_erf(x2); x3 = gelu_erf(x3); }
                    if (sizeof(OutT) == 2)
                        *reinterpret_cast<__half2*>(o1 + ni * 8) = __floats2half2_rn(x2, x3);
                    else
                        *reinterpret_cast<float2*>(o1 + ni * 8) = make_float2(x2, x3);
                }
            }
        }
    }
}

// ---------------- launch ----------------------------------------------------
struct AuxRes {
    cudaStream_t s2;
    cudaEvent_t fork, w1, w2;
    AuxRes() {
        cudaStreamCreateWithFlags(&s2, cudaStreamNonBlocking);
        cudaEventCreateWithFlags(&fork, cudaEventDisableTiming);
        cudaEventCreateWithFlags(&w1, cudaEventDisableTiming);
        cudaEventCreateWithFlags(&w2, cudaEventDisableTiming);
    }
};

extern "C" void kernel_launch(void* const* d_in, const int* in_sizes, int n_in,
                              void* d_out, int out_size) {
    const float* x  = (const float*)d_in[0];
    const float* Wg = (const float*)d_in[1];
    const float* bg = (const float*)d_in[2];
    const float* W1 = (const float*)d_in[3];
    const float* b1 = (const float*)d_in[4];
    const float* W2 = (const float*)d_in[5];
    const float* b2 = (const float*)d_in[6];
    float* out = (float*)d_out;

    static AuxRes R;   // magic-static init on first (correctness) call

    void *p_hh, *p_xh, *p_w1h, *p_w2h;
    cudaGetSymbolAddress(&p_hh,  g_hh);
    cudaGetSymbolAddress(&p_xh,  g_xh);
    cudaGetSymbolAddress(&p_w1h, g_w1h);
    cudaGetSymbolAddress(&p_w2h, g_w2h);

    cudaFuncSetAttribute(moe_gemm<DDIM, true, true, false, __half>,
                         cudaFuncAttributeMaxDynamicSharedMemorySize, SM_BYTES);
    cudaFuncSetAttribute(moe_gemm<HDIM, false, false, true, float>,
                         cudaFuncAttributeMaxDynamicSharedMemorySize, SM_BYTES);

    // ---- fork: weight conversions on side stream ----
    cudaEventRecord(R.fork, 0);
    cudaStreamWaitEvent(R.s2, R.fork, 0);
    conv_half_kernel<<<((size_t)NEXP * DDIM * HDIM / 8) / 256, 256, 0, R.s2>>>(
        W1, (__half*)p_w1h);
    cudaEventRecord(R.w1, R.s2);
    conv_half_kernel<<<((size_t)NEXP * DDIM * HDIM / 8) / 256, 256, 0, R.s2>>>(
        W2, (__half*)p_w2h);
    cudaEventRecord(R.w2, R.s2);

    // ---- main stream: zero out + gating chain + x conversion ----
    zero_out_kernel<<<(N_TOK * DDIM / 4) / 256, 256>>>(out);
    reset_kernel<<<1, 32>>>();
    gate_kernel<<<N_TOK / 8, 256>>>(x, Wg, bg);
    offsets_scatter_kernel<<<1, 1024>>>();
    conv_half_kernel<<<((size_t)N_TOK * DDIM / 8) / 256, 256>>>(x, (__half*)p_xh);

    // ---- join W1, GEMM1: h = fp16(gelu(x[perm] @ W1 + b1)) ----
    cudaStreamWaitEvent(0, R.w1, 0);
    moe_gemm<DDIM, true, true, false, __half>
        <<<dim3(32, HDIM / 256, NEXP), 256, SM_BYTES>>>(
        (const __half*)p_xh, (const __half*)p_w1h, b1, (__half*)p_hh, HDIM);

    // ---- join W2, GEMM2 fused-combine: out[tok] += w * (h @ W2 + b2) ----
    cudaStreamWaitEvent(0, R.w2, 0);
    moe_gemm<HDIM, false, false, true, float>
        <<<dim3(32, DDIM / 256, NEXP), 256, SM_BYTES>>>(
        (const __half*)p_hh, (const __half*)p_w2h, b2, out, DDIM);
}